// round 14
// baseline (speedup 1.0000x reference)
#include <cuda_runtime.h>
#include <cstdint>

// CostBuilder: stereo cost-volume construction.
// left, right: (B=4, C=32, H=64, W=128) fp32
// out:         (B, 2C=64, D=48, H, W) fp32
//   out[b, c,   d, h, w] = (w>=d) ? left [b,c,h,w]   : 0
//   out[b, C+c, d, h, w] = (w>=d) ? right[b,c,h,w-d] : 0
//
// R14: zero-smem kernel. R13 showed DRAM% rises as SM-side overhead falls
// (71% -> 73.6% when left blocks dropped smem). Now the right path drops
// smem too: DPB=4 makes the float4-granular shift k=d>>2 block-uniform and
// the sub-shift m=d&3 compile-time, so shifted rows come from 8 warp
// shuffles per pass instead of smem staging+sync+swizzled LDS. L1 carries
// only mandatory LDG + STG; no __syncthreads anywhere.

namespace {
constexpr int B   = 4;
constexpr int C   = 32;
constexpr int H   = 64;
constexpr int W   = 128;
constexpr int D   = 48;              // MAX_DISP / 4
constexpr int HW  = H * W;           // 8192
constexpr int TPB = 256;
constexpr int DPB = 4;               // d values per block (aligned group!)
constexpr int NDG = D / DPB;         // 12 d-groups
constexpr int PASSES = HW / 4 / TPB; // 8 float4 passes per plane
}

__global__ __launch_bounds__(TPB) void cost_builder_kernel(
    const float* __restrict__ left,
    const float* __restrict__ right,
    float* __restrict__ out)
{
    const int g    = blockIdx.x;
    const int dg   = g % NDG;            // d-group 0..11  (d = 4*dg + dd)
    const int bc2  = g / NDG;            // output channel-plane 0..255
    const int b    = bc2 >> 6;
    const int ch   = bc2 & 63;
    const bool is_right = ch >= C;
    const int c    = ch & (C - 1);

    const float* src = (is_right ? right : left) + (size_t)(b * C + c) * HW;
    const float4* src4 = reinterpret_cast<const float4*>(src);

    const int tid  = threadIdx.x;
    const int lane = tid & 31;
    const int w    = lane << 2;          // this lane's w within its row
    const int d0   = dg * DPB;

    const unsigned outbase0 = (unsigned)bc2 * D * HW;
    float4* outp[DPB];
    #pragma unroll
    for (int dd = 0; dd < DPB; ++dd)
        outp[dd] = reinterpret_cast<float4*>(out + outbase0 + (unsigned)(d0 + dd) * HW);

    if (!is_right) {
        // ---- LEFT PATH: d-invariant data, registers only ----
        #pragma unroll
        for (int p = 0; p < PASSES; ++p) {
            const int i = p * TPB + tid;
            const float4 lv = src4[i];
            #pragma unroll
            for (int dd = 0; dd < DPB; ++dd) {
                const int d = d0 + dd;
                float4 v;
                v.x = (w     >= d) ? lv.x : 0.0f;
                v.y = (w + 1 >= d) ? lv.y : 0.0f;
                v.z = (w + 2 >= d) ? lv.z : 0.0f;
                v.w = (w + 3 >= d) ? lv.w : 0.0f;
                __stcs(outp[dd] + i, v);
            }
        }
        return;
    }

    // ---- RIGHT PATH: shuffle-shifted, no smem, no sync ----
    // k = d>>2 = dg (block-uniform). Value at w-d+j lives in lane-k (A, for
    // j>=m) or lane-k-1 (B, for j<m), m = d&3 = dd (compile-time below).
    // Out-of-range shuffle lanes feed only masked (w+j<d) slots.
    const int k = dg;

    #pragma unroll
    for (int p = 0; p < PASSES; ++p) {
        const int i = p * TPB + tid;     // warp = one row (i>>5)
        const float4 rv = src4[i];

        float A0 = __shfl_up_sync(0xFFFFFFFFu, rv.x, k);
        float A1 = __shfl_up_sync(0xFFFFFFFFu, rv.y, k);
        float A2 = __shfl_up_sync(0xFFFFFFFFu, rv.z, k);
        float A3 = __shfl_up_sync(0xFFFFFFFFu, rv.w, k);
        float B0 = __shfl_up_sync(0xFFFFFFFFu, rv.x, k + 1);
        float B1 = __shfl_up_sync(0xFFFFFFFFu, rv.y, k + 1);
        float B2 = __shfl_up_sync(0xFFFFFFFFu, rv.z, k + 1);
        float B3 = __shfl_up_sync(0xFFFFFFFFu, rv.w, k + 1);

        // dd = m = 0: A0 A1 A2 A3
        {
            const int d = d0 + 0;
            float4 v;
            v.x = (w     >= d) ? A0 : 0.0f;
            v.y = (w + 1 >= d) ? A1 : 0.0f;
            v.z = (w + 2 >= d) ? A2 : 0.0f;
            v.w = (w + 3 >= d) ? A3 : 0.0f;
            __stcs(outp[0] + i, v);
        }
        // dd = m = 1: B3 A0 A1 A2
        {
            const int d = d0 + 1;
            float4 v;
            v.x = (w     >= d) ? B3 : 0.0f;
            v.y = (w + 1 >= d) ? A0 : 0.0f;
            v.z = (w + 2 >= d) ? A1 : 0.0f;
            v.w = (w + 3 >= d) ? A2 : 0.0f;
            __stcs(outp[1] + i, v);
        }
        // dd = m = 2: B2 B3 A0 A1
        {
            const int d = d0 + 2;
            float4 v;
            v.x = (w     >= d) ? B2 : 0.0f;
            v.y = (w + 1 >= d) ? B3 : 0.0f;
            v.z = (w + 2 >= d) ? A0 : 0.0f;
            v.w = (w + 3 >= d) ? A1 : 0.0f;
            __stcs(outp[2] + i, v);
        }
        // dd = m = 3: B1 B2 B3 A0
        {
            const int d = d0 + 3;
            float4 v;
            v.x = (w     >= d) ? B1 : 0.0f;
            v.y = (w + 1 >= d) ? B2 : 0.0f;
            v.z = (w + 2 >= d) ? B3 : 0.0f;
            v.w = (w + 3 >= d) ? A0 : 0.0f;
            __stcs(outp[3] + i, v);
        }
    }
}

extern "C" void kernel_launch(void* const* d_in, const int* in_sizes, int n_in,
                              void* d_out, int out_size)
{
    const float* left  = (const float*)d_in[0];
    const float* right = (const float*)d_in[1];
    float* out = (float*)d_out;

    const int grid = (2 * B * C) * NDG;   // 256 planes * 12 d-groups = 3072
    cost_builder_kernel<<<grid, TPB>>>(left, right, out);
}